// round 15
// baseline (speedup 1.0000x reference)
#include <cuda_runtime.h>
#include <cstdint>

// out = softmax(logits * softmax(logits/0.5)) @ V, logits = scale * Q K^T
// q,k,v: [B=4, H=8, N=2048, D=64] fp32.

constexpr int TPB  = 256;
constexpr int MQ   = 16;      // queries per CTA
constexpr int TK   = 128;     // keys per pipeline stage
constexpr int D    = 64;
constexpr int N    = 2048;
constexpr int NT   = N / TK;  // 16 stages
constexpr int BH   = 32;

constexpr int LSTR = 2056;    // fp32 logits row stride (pad 8)
constexpr int KSTR = 72;      // bf16 tile row stride (64 + 8 pad) -> 144 B/row
constexpr int QSTR = 68;      // fp32 Q staging row stride
constexpr int PSTR = 72;      // pbuf fp32 row stride

constexpr int PLANE_WORDS = TK * (KSTR / 2);   // 4608 u32 (18 KB)
constexpr int STAGE_WORDS = 2 * PLANE_WORDS;   // hi+lo     (36 KB)
constexpr int PLANE_BYTES = PLANE_WORDS * 4;
constexpr int STAGE_BYTES = STAGE_WORDS * 4;

// SMEM float offsets
constexpr int OFF_LOGITS = 0;
constexpr int OFF_QBUF   = OFF_LOGITS + MQ * LSTR;              // 32896
constexpr int OFF_INV2S  = OFF_QBUF + MQ * QSTR;                // 33984
constexpr int OFF_TILES  = ((OFF_INV2S + MQ + 15) / 16) * 16;   // 34000 (16B aligned)
constexpr int SMEM_FLOATS = OFF_TILES + 2 * STAGE_WORDS;        // 52432 (~205 KB)

// Pre-converted bf16 hi/lo planes for K and V: [bh][n][d] packed as bf16x2 words.
constexpr int PLANE_TOTAL = BH * N * D / 2;    // 2,097,152 u32 = 8 MB each
__device__ uint32_t g_khi[PLANE_TOTAL];
__device__ uint32_t g_klo[PLANE_TOTAL];
__device__ uint32_t g_vhi[PLANE_TOTAL];
__device__ uint32_t g_vlo[PLANE_TOTAL];

// ---------------- PTX helpers ----------------
__device__ __forceinline__ uint32_t pack_bf16x2(float lo, float hi) {
    uint32_t r;
    asm("cvt.rn.bf16x2.f32 %0, %1, %2;" : "=r"(r) : "f"(hi), "f"(lo));
    return r;
}
__device__ __forceinline__ void split2(float x, float y, uint32_t& h, uint32_t& l) {
    h = pack_bf16x2(x, y);
    float xh = __uint_as_float(h << 16);
    float yh = __uint_as_float(h & 0xffff0000u);
    l = pack_bf16x2(x - xh, y - yh);
}
__device__ __forceinline__ void mma16816(float c[4], const uint32_t a[4],
                                         uint32_t b0, uint32_t b1) {
    asm volatile(
        "mma.sync.aligned.m16n8k16.row.col.f32.bf16.bf16.f32 "
        "{%0,%1,%2,%3}, {%4,%5,%6,%7}, {%8,%9}, {%0,%1,%2,%3};"
        : "+f"(c[0]), "+f"(c[1]), "+f"(c[2]), "+f"(c[3])
        : "r"(a[0]), "r"(a[1]), "r"(a[2]), "r"(a[3]), "r"(b0), "r"(b1));
}
__device__ __forceinline__ void ldmx4(uint32_t r[4], uint32_t addr) {
    asm volatile("ldmatrix.sync.aligned.m8n8.x4.shared.b16 {%0,%1,%2,%3}, [%4];"
                 : "=r"(r[0]), "=r"(r[1]), "=r"(r[2]), "=r"(r[3]) : "r"(addr));
}
__device__ __forceinline__ void ldmx4_t(uint32_t r[4], uint32_t addr) {
    asm volatile("ldmatrix.sync.aligned.m8n8.x4.trans.shared.b16 {%0,%1,%2,%3}, [%4];"
                 : "=r"(r[0]), "=r"(r[1]), "=r"(r[2]), "=r"(r[3]) : "r"(addr));
}
__device__ __forceinline__ void cp16(uint32_t smem_dst, const void* gsrc) {
    asm volatile("cp.async.cg.shared.global [%0], [%1], 16;"
                 :: "r"(smem_dst), "l"(gsrc) : "memory");
}

// ---------------- Pre-pass: fp32 K,V -> bf16 hi/lo planes ----------------
__global__ __launch_bounds__(256)
void conv_kernel(const float* __restrict__ K, const float* __restrict__ V)
{
    int i = blockIdx.x * 256 + threadIdx.x;     // float4 index
    float4 k4 = reinterpret_cast<const float4*>(K)[i];
    uint32_t h0, l0, h1, l1;
    split2(k4.x, k4.y, h0, l0);
    split2(k4.z, k4.w, h1, l1);
    g_khi[2 * i] = h0; g_khi[2 * i + 1] = h1;
    g_klo[2 * i] = l0; g_klo[2 * i + 1] = l1;
    float4 v4 = reinterpret_cast<const float4*>(V)[i];
    split2(v4.x, v4.y, h0, l0);
    split2(v4.z, v4.w, h1, l1);
    g_vhi[2 * i] = h0; g_vhi[2 * i + 1] = h1;
    g_vlo[2 * i] = l0; g_vlo[2 * i + 1] = l1;
}

// Issue async copies for one TK x D hi/lo tile into stage (byte addr), commit group.
__device__ __forceinline__ void issue_tile(const uint32_t* __restrict__ ghi,
                                           const uint32_t* __restrict__ glo,
                                           uint32_t stageB, int tid)
{
#pragma unroll
    for (int i = 0; i < 8; i++) {
        int idx   = i * 256 + tid;       // 0..2047
        int plane = idx >> 10;           // 0 = hi, 1 = lo
        int rem   = idx & 1023;
        int row   = rem >> 3;            // 0..127
        int c     = rem & 7;             // 16B chunk within row
        const uint32_t* src = (plane ? glo : ghi) + row * (D / 2) + c * 4;
        uint32_t dst = stageB + plane * PLANE_BYTES + row * (KSTR * 2) + c * 16;
        cp16(dst, src);
    }
    asm volatile("cp.async.commit_group;" ::: "memory");
}

__global__ __launch_bounds__(TPB, 1)
void stk_branch_kernel(const float* __restrict__ Q, const float* __restrict__ scale_p,
                       float* __restrict__ O)
{
    extern __shared__ float sm[];
    float* logits = sm + OFF_LOGITS;
    float* qbuf   = sm + OFF_QBUF;
    float* inv2s  = sm + OFF_INV2S;

    const int tid  = threadIdx.x;
    const int wid  = tid >> 5, lane = tid & 31;
    const int gid  = lane >> 2, tg = lane & 3;
    const int lg   = lane >> 3, lr = lane & 7;

    const int bh    = blockIdx.y;
    const int qbase = blockIdx.x * MQ;
    const int base  = bh * (N * D);
    const int baseW = base >> 1;               // u32 word offset into planes
    const float sc  = __ldg(scale_p);

    const uint32_t smemB  = (uint32_t)__cvta_generic_to_shared(sm);
    const uint32_t tilesB = smemB + OFF_TILES * 4;

    // ---- Stage Q fp32 into smem ----
    {
        int o4 = tid << 2;
        int qq = o4 >> 6, dd = o4 & 63;
        float4 qv = *reinterpret_cast<const float4*>(Q + base + (qbase + qq) * D + dd);
        *reinterpret_cast<float4*>(&qbuf[qq * QSTR + dd]) = qv;
    }
    __syncthreads();

    // ---- Build Q A-fragments (hi/lo) in registers: 4 k-steps ----
    uint32_t aQh[4][4], aQl[4][4];
#pragma unroll
    for (int ks = 0; ks < 4; ks++) {
        int c0 = ks * 16 + 2 * tg;
        float2 v00 = *reinterpret_cast<const float2*>(&qbuf[gid * QSTR + c0]);
        float2 v10 = *reinterpret_cast<const float2*>(&qbuf[(gid + 8) * QSTR + c0]);
        float2 v01 = *reinterpret_cast<const float2*>(&qbuf[gid * QSTR + c0 + 8]);
        float2 v11 = *reinterpret_cast<const float2*>(&qbuf[(gid + 8) * QSTR + c0 + 8]);
        split2(v00.x, v00.y, aQh[ks][0], aQl[ks][0]);
        split2(v10.x, v10.y, aQh[ks][1], aQl[ks][1]);
        split2(v01.x, v01.y, aQh[ks][2], aQl[ks][2]);
        split2(v11.x, v11.y, aQh[ks][3], aQl[ks][3]);
    }

    // ---- Phase 1: logits = sc * Q K^T (cp.async double-buffered) ----
    issue_tile(g_khi + baseW, g_klo + baseW, tilesB, tid);
    for (int t = 0; t < NT; t++) {
        if (t + 1 < NT) {
            int offW = baseW + (t + 1) * TK * (D / 2);
            issue_tile(g_khi + offW, g_klo + offW, tilesB + ((t + 1) & 1) * STAGE_BYTES, tid);
            asm volatile("cp.async.wait_group 1;" ::: "memory");
        } else {
            asm volatile("cp.async.wait_group 0;" ::: "memory");
        }
        __syncthreads();

        const uint32_t hiB = tilesB + (t & 1) * STAGE_BYTES;
        const uint32_t loB = hiB + PLANE_BYTES;

        // 3 independent accumulator chains per 8-col output -> 6 chains/warp
        float ca0[4] = {0,0,0,0}, cb0[4] = {0,0,0,0}, cc0[4] = {0,0,0,0};
        float ca1[4] = {0,0,0,0}, cb1[4] = {0,0,0,0}, cc1[4] = {0,0,0,0};
        uint32_t rowv = wid * 16 + lr + ((lg >= 2) ? 8 : 0);
#pragma unroll
        for (int ks = 0; ks < 4; ks++) {
            uint32_t colv = ks * 16 + ((lg & 1) ? 8 : 0);
            uint32_t off  = rowv * (KSTR * 2) + colv * 2;
            uint32_t bhr[4], blr[4];
            ldmx4(bhr, hiB + off);
            ldmx4(blr, loB + off);
            mma16816(ca0, aQh[ks], bhr[0], bhr[1]);
            mma16816(cb0, aQh[ks], blr[0], blr[1]);
            mma16816(cc0, aQl[ks], bhr[0], bhr[1]);
            mma16816(ca1, aQh[ks], bhr[2], bhr[3]);
            mma16816(cb1, aQh[ks], blr[2], blr[3]);
            mma16816(cc1, aQl[ks], bhr[2], bhr[3]);
        }
        int nb = t * TK + wid * 16;
        *reinterpret_cast<float2*>(&logits[gid * LSTR + nb + 2 * tg]) =
            make_float2((ca0[0] + cb0[0] + cc0[0]) * sc, (ca0[1] + cb0[1] + cc0[1]) * sc);
        *reinterpret_cast<float2*>(&logits[(gid + 8) * LSTR + nb + 2 * tg]) =
            make_float2((ca0[2] + cb0[2] + cc0[2]) * sc, (ca0[3] + cb0[3] + cc0[3]) * sc);
        *reinterpret_cast<float2*>(&logits[gid * LSTR + nb + 8 + 2 * tg]) =
            make_float2((ca1[0] + cb1[0] + cc1[0]) * sc, (ca1[1] + cb1[1] + cc1[1]) * sc);
        *reinterpret_cast<float2*>(&logits[(gid + 8) * LSTR + nb + 8 + 2 * tg]) =
            make_float2((ca1[2] + cb1[2] + cc1[2]) * sc, (ca1[3] + cb1[3] + cc1[3]) * sc);
        __syncthreads();
    }

    // ---- Phase 2: per-row double softmax in place (warp w owns rows 2w, 2w+1) ----
    {
#pragma unroll
        for (int rr = 0; rr < 2; rr++) {
            float* L = logits + ((wid << 1) + rr) * LSTR;

            float m = -1e30f;
            for (int it = 0; it < 16; it++) {
                float4 x = *reinterpret_cast<const float4*>(&L[(it * 32 + lane) << 2]);
                m = fmaxf(m, fmaxf(fmaxf(x.x, x.y), fmaxf(x.z, x.w)));
            }
#pragma unroll
            for (int o = 16; o; o >>= 1) m = fmaxf(m, __shfl_xor_sync(0xffffffffu, m, o));

            float s = 0.f;
            for (int it = 0; it < 16; it++) {
                float4 x = *reinterpret_cast<const float4*>(&L[(it * 32 + lane) << 2]);
                s += __expf(2.f * (x.x - m)) + __expf(2.f * (x.y - m))
                   + __expf(2.f * (x.z - m)) + __expf(2.f * (x.w - m));
            }
#pragma unroll
            for (int o = 16; o; o >>= 1) s += __shfl_xor_sync(0xffffffffu, s, o);
            float inv1 = 1.f / s;

            float m2 = -1e30f;
            for (int it = 0; it < 16; it++) {
                float4* p4 = reinterpret_cast<float4*>(&L[(it * 32 + lane) << 2]);
                float4 x = *p4;
                x.x = x.x * (__expf(2.f * (x.x - m)) * inv1);
                x.y = x.y * (__expf(2.f * (x.y - m)) * inv1);
                x.z = x.z * (__expf(2.f * (x.z - m)) * inv1);
                x.w = x.w * (__expf(2.f * (x.w - m)) * inv1);
                *p4 = x;
                m2 = fmaxf(m2, fmaxf(fmaxf(x.x, x.y), fmaxf(x.z, x.w)));
            }
#pragma unroll
            for (int o = 16; o; o >>= 1) m2 = fmaxf(m2, __shfl_xor_sync(0xffffffffu, m2, o));

            float s2 = 0.f;
            for (int it = 0; it < 16; it++) {
                float4* p4 = reinterpret_cast<float4*>(&L[(it * 32 + lane) << 2]);
                float4 x = *p4;
                x.x = __expf(x.x - m2); x.y = __expf(x.y - m2);
                x.z = __expf(x.z - m2); x.w = __expf(x.w - m2);
                *p4 = x;
                s2 += x.x + x.y + x.z + x.w;
            }
#pragma unroll
            for (int o = 16; o; o >>= 1) s2 += __shfl_xor_sync(0xffffffffu, s2, o);
            if (lane == 0) inv2s[(wid << 1) + rr] = 1.f / s2;
        }
    }

    // ---- Phase 3: O = P V (cp.async double-buffered, warp-split over keys) ----
    float oc[8][4];
#pragma unroll
    for (int j = 0; j < 8; j++)
#pragma unroll
        for (int i = 0; i < 4; i++) oc[j][i] = 0.f;

    issue_tile(g_vhi + baseW, g_vlo + baseW, tilesB, tid);
    for (int t = 0; t < NT; t++) {
        if (t + 1 < NT) {
            int offW = baseW + (t + 1) * TK * (D / 2);
            issue_tile(g_vhi + offW, g_vlo + offW, tilesB + ((t + 1) & 1) * STAGE_BYTES, tid);
            asm volatile("cp.async.wait_group 1;" ::: "memory");
        } else {
            asm volatile("cp.async.wait_group 0;" ::: "memory");
        }
        __syncthreads();

        const uint32_t hiB = tilesB + (t & 1) * STAGE_BYTES;
        const uint32_t loB = hiB + PLANE_BYTES;

        int kloc = wid * 16;
        int kg   = t * TK + kloc;
        float2 p00 = *reinterpret_cast<const float2*>(&logits[gid * LSTR + kg + 2 * tg]);
        float2 p10 = *reinterpret_cast<const float2*>(&logits[(gid + 8) * LSTR + kg + 2 * tg]);
        float2 p01 = *reinterpret_cast<const float2*>(&logits[gid * LSTR + kg + 8 + 2 * tg]);
        float2 p11 = *reinterpret_cast<const float2*>(&logits[(gid + 8) * LSTR + kg + 8 + 2 * tg]);
        uint32_t ah[4], al[4];
        split2(p00.x, p00.y, ah[0], al[0]);
        split2(p10.x, p10.y, ah[1], al[1]);
        split2(p01.x, p01.y, ah[2], al[2]);
        split2(p11.x, p11.y, ah[3], al[3]);

        uint32_t rowv = kloc + lr + ((lg & 1) ? 8 : 0);
#pragma unroll
        for (int j = 0; j < 4; j++) {
            uint32_t colv = j * 16 + ((lg >= 2) ? 8 : 0);
            uint32_t off  = rowv * (KSTR * 2) + colv * 2;
            uint32_t bhr[4], blr[4];
            ldmx4_t(bhr, hiB + off);
            ldmx4_t(blr, loB + off);
            mma16816(oc[2 * j],     ah, bhr[0], bhr[1]);
            mma16816(oc[2 * j],     ah, blr[0], blr[1]);
            mma16816(oc[2 * j],     al, bhr[0], bhr[1]);
            mma16816(oc[2 * j + 1], ah, bhr[2], bhr[3]);
            mma16816(oc[2 * j + 1], ah, blr[2], blr[3]);
            mma16816(oc[2 * j + 1], al, bhr[2], bhr[3]);
        }
        __syncthreads();
    }

    // ---- Cross-warp reduction of partial O (reuse tile buffer) ----
    float* pbuf = sm + OFF_TILES;
#pragma unroll
    for (int dt = 0; dt < 8; dt++) {
        *reinterpret_cast<float2*>(&pbuf[wid * (MQ * PSTR) + gid * PSTR + dt * 8 + 2 * tg]) =
            make_float2(oc[dt][0], oc[dt][1]);
        *reinterpret_cast<float2*>(&pbuf[wid * (MQ * PSTR) + (gid + 8) * PSTR + dt * 8 + 2 * tg]) =
            make_float2(oc[dt][2], oc[dt][3]);
    }
    __syncthreads();

    {
        int o4 = tid << 2;
        int qq = o4 >> 6, dd = o4 & 63;
        float r0 = 0.f, r1 = 0.f, r2 = 0.f, r3 = 0.f;
#pragma unroll
        for (int w = 0; w < 8; w++) {
            const float* p = &pbuf[w * (MQ * PSTR) + qq * PSTR + dd];
            r0 += p[0]; r1 += p[1]; r2 += p[2]; r3 += p[3];
        }
        float iv = inv2s[qq];
        *reinterpret_cast<float4*>(O + base + (qbase + qq) * D + dd) =
            make_float4(r0 * iv, r1 * iv, r2 * iv, r3 * iv);
    }
}

extern "C" void kernel_launch(void* const* d_in, const int* in_sizes, int n_in,
                              void* d_out, int out_size)
{
    const float* q  = (const float*)d_in[0];
    const float* k  = (const float*)d_in[1];
    const float* v  = (const float*)d_in[2];
    const float* sc = (const float*)d_in[3];
    float* o = (float*)d_out;

    // Pre-pass: convert K and V to bf16 hi/lo planes once.
    conv_kernel<<<(BH * N * D / 4) / 256, 256>>>(k, v);

    size_t smem = (size_t)SMEM_FLOATS * sizeof(float);
    cudaFuncSetAttribute(stk_branch_kernel,
                         cudaFuncAttributeMaxDynamicSharedMemorySize, (int)smem);
    dim3 grid(N / MQ, BH);
    stk_branch_kernel<<<grid, TPB, smem>>>(q, sc, o);
}

// round 16
// speedup vs baseline: 1.4953x; 1.4953x over previous
#include <cuda_runtime.h>
#include <cstdint>

// out = softmax(logits * softmax(logits/0.5)) @ V, logits = scale * Q K^T
// q,k,v: [B=4, H=8, N=2048, D=64] fp32.

constexpr int TPB  = 256;
constexpr int MQ   = 16;      // queries per CTA
constexpr int TK   = 256;     // keys per SMEM tile
constexpr int D    = 64;
constexpr int N    = 2048;
constexpr int NT   = N / TK;  // 8
constexpr int BH   = 32;

constexpr int LSTR = 2056;    // fp32 logits row stride (pad 8)
constexpr int KSTR = 72;      // bf16 tile row stride (64 + 8 pad) -> 144 B/row
constexpr int QSTR = 68;      // fp32 Q staging row stride
constexpr int PSTR = 72;      // pbuf fp32 row stride

constexpr int PLANE_WORDS = TK * (KSTR / 2);   // 9216 u32 = 36 KB
constexpr int PLANE_BYTES = PLANE_WORDS * 4;

// SMEM float offsets
constexpr int OFF_LOGITS = 0;
constexpr int OFF_QBUF   = OFF_LOGITS + MQ * LSTR;     // 32896
constexpr int OFF_M2S    = OFF_QBUF + MQ * QSTR;       // 33984 (+16)
constexpr int OFF_S2BUF  = OFF_M2S + MQ;               // 34000 (+128)
constexpr int OFF_TILES  = OFF_S2BUF + 128;            // 34128 (16B aligned)
constexpr int SMEM_FLOATS = OFF_TILES + 2 * PLANE_WORDS;   // 52560 (~210 KB)

// Pre-converted bf16 hi/lo planes for K and V: [bh][n][d] packed as bf16x2 words.
constexpr int PLANE_TOTAL = BH * N * D / 2;    // 8 MB each
__device__ uint32_t g_khi[PLANE_TOTAL];
__device__ uint32_t g_klo[PLANE_TOTAL];
__device__ uint32_t g_vhi[PLANE_TOTAL];
__device__ uint32_t g_vlo[PLANE_TOTAL];

// ---------------- PTX helpers ----------------
__device__ __forceinline__ uint32_t pack_bf16x2(float lo, float hi) {
    uint32_t r;
    asm("cvt.rn.bf16x2.f32 %0, %1, %2;" : "=r"(r) : "f"(hi), "f"(lo));
    return r;
}
__device__ __forceinline__ void split2(float x, float y, uint32_t& h, uint32_t& l) {
    h = pack_bf16x2(x, y);
    float xh = __uint_as_float(h << 16);
    float yh = __uint_as_float(h & 0xffff0000u);
    l = pack_bf16x2(x - xh, y - yh);
}
__device__ __forceinline__ void mma16816(float c[4], const uint32_t a[4],
                                         uint32_t b0, uint32_t b1) {
    asm volatile(
        "mma.sync.aligned.m16n8k16.row.col.f32.bf16.bf16.f32 "
        "{%0,%1,%2,%3}, {%4,%5,%6,%7}, {%8,%9}, {%0,%1,%2,%3};"
        : "+f"(c[0]), "+f"(c[1]), "+f"(c[2]), "+f"(c[3])
        : "r"(a[0]), "r"(a[1]), "r"(a[2]), "r"(a[3]), "r"(b0), "r"(b1));
}
__device__ __forceinline__ void ldmx4(uint32_t r[4], uint32_t addr) {
    asm volatile("ldmatrix.sync.aligned.m8n8.x4.shared.b16 {%0,%1,%2,%3}, [%4];"
                 : "=r"(r[0]), "=r"(r[1]), "=r"(r[2]), "=r"(r[3]) : "r"(addr));
}
__device__ __forceinline__ void ldmx4_t(uint32_t r[4], uint32_t addr) {
    asm volatile("ldmatrix.sync.aligned.m8n8.x4.trans.shared.b16 {%0,%1,%2,%3}, [%4];"
                 : "=r"(r[0]), "=r"(r[1]), "=r"(r[2]), "=r"(r[3]) : "r"(addr));
}
__device__ __forceinline__ void cp16(uint32_t smem_dst, const void* gsrc) {
    asm volatile("cp.async.cg.shared.global [%0], [%1], 16;"
                 :: "r"(smem_dst), "l"(gsrc) : "memory");
}

// ---------------- Pre-pass: fp32 K,V -> bf16 hi/lo planes ----------------
__global__ __launch_bounds__(256)
void conv_kernel(const float* __restrict__ K, const float* __restrict__ V)
{
    int i = blockIdx.x * 256 + threadIdx.x;     // float4 index
    float4 k4 = reinterpret_cast<const float4*>(K)[i];
    uint32_t h0, l0, h1, l1;
    split2(k4.x, k4.y, h0, l0);
    split2(k4.z, k4.w, h1, l1);
    g_khi[2 * i] = h0; g_khi[2 * i + 1] = h1;
    g_klo[2 * i] = l0; g_klo[2 * i + 1] = l1;
    float4 v4 = reinterpret_cast<const float4*>(V)[i];
    split2(v4.x, v4.y, h0, l0);
    split2(v4.z, v4.w, h1, l1);
    g_vhi[2 * i] = h0; g_vhi[2 * i + 1] = h1;
    g_vlo[2 * i] = l0; g_vlo[2 * i + 1] = l1;
}

// Async-copy one TK x D hi/lo tile (data bytes only; pad skipped) into tiles smem.
__device__ __forceinline__ void issue_tile(const uint32_t* __restrict__ ghi,
                                           const uint32_t* __restrict__ glo,
                                           uint32_t tilesB, int tid)
{
#pragma unroll
    for (int i = 0; i < 16; i++) {
        int idx   = i * 256 + tid;       // 0..4095
        int plane = idx >> 11;           // 0 = hi, 1 = lo
        int rem   = idx & 2047;
        int row   = rem >> 3;            // 0..255
        int c     = rem & 7;             // 16B chunk within row
        const uint32_t* src = (plane ? glo : ghi) + row * (D / 2) + c * 4;
        uint32_t dst = tilesB + plane * PLANE_BYTES + row * (KSTR * 2) + c * 16;
        cp16(dst, src);
    }
    asm volatile("cp.async.commit_group;" ::: "memory");
}

__global__ __launch_bounds__(TPB, 1)
void stk_branch_kernel(const float* __restrict__ Q, const float* __restrict__ scale_p,
                       float* __restrict__ O)
{
    extern __shared__ float sm[];
    float* logits = sm + OFF_LOGITS;
    float* qbuf   = sm + OFF_QBUF;
    float* m2s    = sm + OFF_M2S;
    float* s2buf  = sm + OFF_S2BUF;

    const int tid  = threadIdx.x;
    const int wid  = tid >> 5, lane = tid & 31;
    const int gid  = lane >> 2, tg = lane & 3;
    const int lg   = lane >> 3, lr = lane & 7;

    const int bh    = blockIdx.y;
    const int qbase = blockIdx.x * MQ;
    const int base  = bh * (N * D);
    const int baseW = base >> 1;               // u32 word offset into planes
    const float sc  = __ldg(scale_p);

    const uint32_t smemB  = (uint32_t)__cvta_generic_to_shared(sm);
    const uint32_t tilesB = smemB + OFF_TILES * 4;

    // ---- Stage Q fp32 into smem ----
    {
        int o4 = tid << 2;
        int qq = o4 >> 6, dd = o4 & 63;
        float4 qv = *reinterpret_cast<const float4*>(Q + base + (qbase + qq) * D + dd);
        *reinterpret_cast<float4*>(&qbuf[qq * QSTR + dd]) = qv;
    }
    __syncthreads();

    // ---- Build Q A-fragments (hi/lo): 4 k-steps ----
    uint32_t aQh[4][4], aQl[4][4];
#pragma unroll
    for (int ks = 0; ks < 4; ks++) {
        int c0 = ks * 16 + 2 * tg;
        float2 v00 = *reinterpret_cast<const float2*>(&qbuf[gid * QSTR + c0]);
        float2 v10 = *reinterpret_cast<const float2*>(&qbuf[(gid + 8) * QSTR + c0]);
        float2 v01 = *reinterpret_cast<const float2*>(&qbuf[gid * QSTR + c0 + 8]);
        float2 v11 = *reinterpret_cast<const float2*>(&qbuf[(gid + 8) * QSTR + c0 + 8]);
        split2(v00.x, v00.y, aQh[ks][0], aQl[ks][0]);
        split2(v10.x, v10.y, aQh[ks][1], aQl[ks][1]);
        split2(v01.x, v01.y, aQh[ks][2], aQl[ks][2]);
        split2(v11.x, v11.y, aQh[ks][3], aQl[ks][3]);
    }

    // ---- Phase 1: logits = sc * Q K^T ----
    for (int t = 0; t < NT; t++) {
        __syncthreads();                      // prev MMAs done reading tiles
        issue_tile(g_khi + baseW + t * TK * (D / 2),
                   g_klo + baseW + t * TK * (D / 2), tilesB, tid);
        asm volatile("cp.async.wait_group 0;" ::: "memory");
        __syncthreads();

        const uint32_t hiB = tilesB;
        const uint32_t loB = tilesB + PLANE_BYTES;
        int ns = wid * 32;
#pragma unroll
        for (int j = 0; j < 2; j++) {
            int np = ns + j * 16;
            // 3 independent accumulator chains per 8-col block
            float ca0[4] = {0,0,0,0}, cb0[4] = {0,0,0,0}, cc0[4] = {0,0,0,0};
            float ca1[4] = {0,0,0,0}, cb1[4] = {0,0,0,0}, cc1[4] = {0,0,0,0};
            uint32_t rowv = np + lr + ((lg >= 2) ? 8 : 0);
#pragma unroll
            for (int ks = 0; ks < 4; ks++) {
                uint32_t colv = ks * 16 + ((lg & 1) ? 8 : 0);
                uint32_t off  = rowv * (KSTR * 2) + colv * 2;
                uint32_t bhr[4], blr[4];
                ldmx4(bhr, hiB + off);
                ldmx4(blr, loB + off);
                mma16816(ca0, aQh[ks], bhr[0], bhr[1]);
                mma16816(cb0, aQh[ks], blr[0], blr[1]);
                mma16816(cc0, aQl[ks], bhr[0], bhr[1]);
                mma16816(ca1, aQh[ks], bhr[2], bhr[3]);
                mma16816(cb1, aQh[ks], blr[2], blr[3]);
                mma16816(cc1, aQl[ks], bhr[2], bhr[3]);
            }
            int nb = t * TK + np;
            *reinterpret_cast<float2*>(&logits[gid * LSTR + nb + 2 * tg]) =
                make_float2((ca0[0]+cb0[0]+cc0[0]) * sc, (ca0[1]+cb0[1]+cc0[1]) * sc);
            *reinterpret_cast<float2*>(&logits[(gid + 8) * LSTR + nb + 2 * tg]) =
                make_float2((ca0[2]+cb0[2]+cc0[2]) * sc, (ca0[3]+cb0[3]+cc0[3]) * sc);
            *reinterpret_cast<float2*>(&logits[gid * LSTR + nb + 8 + 2 * tg]) =
                make_float2((ca1[0]+cb1[0]+cc1[0]) * sc, (ca1[1]+cb1[1]+cc1[1]) * sc);
            *reinterpret_cast<float2*>(&logits[(gid + 8) * LSTR + nb + 8 + 2 * tg]) =
                make_float2((ca1[2]+cb1[2]+cc1[2]) * sc, (ca1[3]+cb1[3]+cc1[3]) * sc);
        }
    }
    __syncthreads();

    // ---- Phase 2: 3 passes per row: max; sum exp; g-write + m2 (warp w: rows 2w,2w+1).
    //      Final exp(g - m2) is fused into phase 3; row sums accumulated there. ----
    {
#pragma unroll
        for (int rr = 0; rr < 2; rr++) {
            int row = (wid << 1) + rr;
            float* L = logits + row * LSTR;

            float m = -1e30f;
            for (int it = 0; it < 16; it++) {
                float4 x = *reinterpret_cast<const float4*>(&L[(it * 32 + lane) << 2]);
                m = fmaxf(m, fmaxf(fmaxf(x.x, x.y), fmaxf(x.z, x.w)));
            }
#pragma unroll
            for (int o = 16; o; o >>= 1) m = fmaxf(m, __shfl_xor_sync(0xffffffffu, m, o));

            float s = 0.f;
            for (int it = 0; it < 16; it++) {
                float4 x = *reinterpret_cast<const float4*>(&L[(it * 32 + lane) << 2]);
                s += __expf(2.f * (x.x - m)) + __expf(2.f * (x.y - m))
                   + __expf(2.f * (x.z - m)) + __expf(2.f * (x.w - m));
            }
#pragma unroll
            for (int o = 16; o; o >>= 1) s += __shfl_xor_sync(0xffffffffu, s, o);
            float inv1 = 1.f / s;

            float m2 = -1e30f;
            for (int it = 0; it < 16; it++) {
                float4* p4 = reinterpret_cast<float4*>(&L[(it * 32 + lane) << 2]);
                float4 x = *p4;
                x.x = x.x * (__expf(2.f * (x.x - m)) * inv1);
                x.y = x.y * (__expf(2.f * (x.y - m)) * inv1);
                x.z = x.z * (__expf(2.f * (x.z - m)) * inv1);
                x.w = x.w * (__expf(2.f * (x.w - m)) * inv1);
                *p4 = x;
                m2 = fmaxf(m2, fmaxf(fmaxf(x.x, x.y), fmaxf(x.z, x.w)));
            }
#pragma unroll
            for (int o = 16; o; o >>= 1) m2 = fmaxf(m2, __shfl_xor_sync(0xffffffffu, m2, o));
            if (lane == 0) m2s[row] = m2;
        }
    }

    // ---- Phase 3: O = P V with P = exp(g - m2) computed inline; track row sums ----
    float oc[8][4];
#pragma unroll
    for (int j = 0; j < 8; j++)
#pragma unroll
        for (int i = 0; i < 4; i++) oc[j][i] = 0.f;
    float sA = 0.f, sB = 0.f;                 // partial Σexp for rows gid, gid+8
    float m2a, m2b;

    for (int t = 0; t < NT; t++) {
        __syncthreads();                      // t=0: g/m2s visible; t>0: tiles WAR
        if (t == 0) { m2a = m2s[gid]; m2b = m2s[gid + 8]; }
        issue_tile(g_vhi + baseW + t * TK * (D / 2),
                   g_vlo + baseW + t * TK * (D / 2), tilesB, tid);
        asm volatile("cp.async.wait_group 0;" ::: "memory");
        __syncthreads();

        const uint32_t hiB = tilesB;
        const uint32_t loB = tilesB + PLANE_BYTES;

        int kb = wid * 32;
#pragma unroll
        for (int ks2 = 0; ks2 < 2; ks2++) {
            int kloc = kb + ks2 * 16;
            int kg   = t * TK + kloc;
            float2 p00 = *reinterpret_cast<const float2*>(&logits[gid * LSTR + kg + 2 * tg]);
            float2 p10 = *reinterpret_cast<const float2*>(&logits[(gid + 8) * LSTR + kg + 2 * tg]);
            float2 p01 = *reinterpret_cast<const float2*>(&logits[gid * LSTR + kg + 8 + 2 * tg]);
            float2 p11 = *reinterpret_cast<const float2*>(&logits[(gid + 8) * LSTR + kg + 8 + 2 * tg]);
            // inline exp (this is the deleted softmax pass 4, overlapped with MMAs)
            p00.x = __expf(p00.x - m2a); p00.y = __expf(p00.y - m2a);
            p01.x = __expf(p01.x - m2a); p01.y = __expf(p01.y - m2a);
            p10.x = __expf(p10.x - m2b); p10.y = __expf(p10.y - m2b);
            p11.x = __expf(p11.x - m2b); p11.y = __expf(p11.y - m2b);
            sA += p00.x + p00.y + p01.x + p01.y;
            sB += p10.x + p10.y + p11.x + p11.y;

            uint32_t ah[4], al[4];
            split2(p00.x, p00.y, ah[0], al[0]);
            split2(p10.x, p10.y, ah[1], al[1]);
            split2(p01.x, p01.y, ah[2], al[2]);
            split2(p11.x, p11.y, ah[3], al[3]);

            uint32_t rowv = kloc + lr + ((lg & 1) ? 8 : 0);
#pragma unroll
            for (int j = 0; j < 4; j++) {
                uint32_t colv = j * 16 + ((lg >= 2) ? 8 : 0);
                uint32_t off  = rowv * (KSTR * 2) + colv * 2;
                uint32_t bhr[4], blr[4];
                ldmx4_t(bhr, hiB + off);
                ldmx4_t(blr, loB + off);
                mma16816(oc[2 * j],     ah, bhr[0], bhr[1]);
                mma16816(oc[2 * j],     ah, blr[0], blr[1]);
                mma16816(oc[2 * j],     al, bhr[0], bhr[1]);
                mma16816(oc[2 * j + 1], ah, bhr[2], bhr[3]);
                mma16816(oc[2 * j + 1], ah, blr[2], blr[3]);
                mma16816(oc[2 * j + 1], al, bhr[2], bhr[3]);
            }
        }
    }

    // per-warp row-sum reduction over tg lanes (same gid)
    sA += __shfl_xor_sync(0xffffffffu, sA, 1);
    sA += __shfl_xor_sync(0xffffffffu, sA, 2);
    sB += __shfl_xor_sync(0xffffffffu, sB, 1);
    sB += __shfl_xor_sync(0xffffffffu, sB, 2);
    if (tg == 0) {
        s2buf[wid * MQ + gid]     = sA;
        s2buf[wid * MQ + gid + 8] = sB;
    }

    // ---- Cross-warp reduction of partial O + row sums (reuse tile buffer) ----
    __syncthreads();
    float* pbuf = sm + OFF_TILES;
#pragma unroll
    for (int dt = 0; dt < 8; dt++) {
        *reinterpret_cast<float2*>(&pbuf[wid * (MQ * PSTR) + gid * PSTR + dt * 8 + 2 * tg]) =
            make_float2(oc[dt][0], oc[dt][1]);
        *reinterpret_cast<float2*>(&pbuf[wid * (MQ * PSTR) + (gid + 8) * PSTR + dt * 8 + 2 * tg]) =
            make_float2(oc[dt][2], oc[dt][3]);
    }
    __syncthreads();

    {
        int o4 = tid << 2;
        int qq = o4 >> 6, dd = o4 & 63;
        float r0 = 0.f, r1 = 0.f, r2 = 0.f, r3 = 0.f;
        float s2 = 0.f;
#pragma unroll
        for (int w = 0; w < 8; w++) {
            const float* p = &pbuf[w * (MQ * PSTR) + qq * PSTR + dd];
            r0 += p[0]; r1 += p[1]; r2 += p[2]; r3 += p[3];
            s2 += s2buf[w * MQ + qq];
        }
        float iv = 1.f / s2;
        *reinterpret_cast<float4*>(O + base + (qbase + qq) * D + dd) =
            make_float4(r0 * iv, r1 * iv, r2 * iv, r3 * iv);
    }
}

extern "C" void kernel_launch(void* const* d_in, const int* in_sizes, int n_in,
                              void* d_out, int out_size)
{
    const float* q  = (const float*)d_in[0];
    const float* k  = (const float*)d_in[1];
    const float* v  = (const float*)d_in[2];
    const float* sc = (const float*)d_in[3];
    float* o = (float*)d_out;

    // Pre-pass: convert K and V to bf16 hi/lo planes once.
    conv_kernel<<<(BH * N * D / 4) / 256, 256>>>(k, v);

    size_t smem = (size_t)SMEM_FLOATS * sizeof(float);
    cudaFuncSetAttribute(stk_branch_kernel,
                         cudaFuncAttributeMaxDynamicSharedMemorySize, (int)smem);
    dim3 grid(N / MQ, BH);
    stk_branch_kernel<<<grid, TPB, smem>>>(q, sc, o);
}